// round 14
// baseline (speedup 1.0000x reference)
#include <cuda_runtime.h>
#include <cuda_bf16.h>
#include <cstdint>
#include <cstddef>

#define B 256
#define L 2048
#define H 128
#define V 32000
#define BL (B * L)
#define TOK 128

typedef unsigned long long u64;
typedef uint32_t u32;

// ---------------------------------------------------------------------------
// helpers
// ---------------------------------------------------------------------------
__device__ __forceinline__ u32 smem_u32(const void* p) {
    return (u32)__cvta_generic_to_shared(p);
}

__device__ __forceinline__ void ldsm_x4(u32* r, u32 addr) {
    asm volatile("ldmatrix.sync.aligned.m8n8.x4.shared.b16 {%0,%1,%2,%3}, [%4];"
                 : "=r"(r[0]), "=r"(r[1]), "=r"(r[2]), "=r"(r[3]) : "r"(addr));
}

__device__ __forceinline__ void mma16816(float* d, const u32* a, u32 b0, u32 b1) {
    asm volatile(
        "mma.sync.aligned.m16n8k16.row.col.f32.bf16.bf16.f32 "
        "{%0,%1,%2,%3}, {%4,%5,%6,%7}, {%8,%9}, {%0,%1,%2,%3};"
        : "+f"(d[0]), "+f"(d[1]), "+f"(d[2]), "+f"(d[3])
        : "r"(a[0]), "r"(a[1]), "r"(a[2]), "r"(a[3]), "r"(b0), "r"(b1));
}

__device__ __forceinline__ void cp16(u32 dst, const void* src) {
    asm volatile("cp.async.cg.shared.global [%0], [%1], 16;" :: "r"(dst), "l"(src));
}

// Packed dual-FMA (scan kernel).
__device__ __forceinline__ float2 ffma2(float2 a, float2 b, float2 c) {
    float2 d;
    asm("fma.rn.f32x2 %0, %1, %2, %3;"
        : "=l"(*(u64*)&d)
        : "l"(*(u64*)&a), "l"(*(u64*)&b), "l"(*(u64*)&c));
    return d;
}

// 3-way bf16 split: x = a0+a1+a2 + O(2^-27 * x)
__device__ __forceinline__ void split3(float x, __nv_bfloat16* a) {
    a[0] = __float2bfloat16(x);
    float r = x - __bfloat162float(a[0]);
    a[1] = __float2bfloat16(r);  r -= __bfloat162float(a[1]);
    a[2] = __float2bfloat16(r);
}
__device__ __forceinline__ u32 pack_bf2(__nv_bfloat16 lo, __nv_bfloat16 hi) {
    __nv_bfloat162 p;
    p.x = lo; p.y = hi;
    return *(u32*)&p;
}

// XOR chunk swizzles: conflict-free ldmatrix on natural row strides.
__device__ __forceinline__ u32 swz256(int row, int kb) {
    return (u32)(row * 256 + ((((kb >> 4) ^ (row & 7)) << 4) | (kb & 15)));
}
__device__ __forceinline__ u32 swz128(int row, int kb) {
    return (u32)(row * 128 + ((((kb >> 4) ^ (row & 7)) << 4) | (kb & 15)));
}

// ---------------------------------------------------------------------------
// Scratch device globals.
// ---------------------------------------------------------------------------
__device__ float g_h[(size_t)BL * H];
__device__ float g_rp[B * H];
// Pre-split, pre-swizzled weight part-tiles (3 parts):
__device__ unsigned char g_W1s[4 * 3 * 16384];
__device__ unsigned char g_W2s[4 * 3 * 16384];
// Wout split (2 bf16 parts), chunked by 128 vocab cols:
// g_Wo: [chunk=250][part=2][128 n-rows x 128 k bf16, swz256 rows] = 16.384 MB
__device__ unsigned char g_Wo[250 * 2 * 32768];

// ---------------------------------------------------------------------------
// Prep: split3 + transpose + swizzle W1/W2.
// ---------------------------------------------------------------------------
__global__ void __launch_bounds__(256) prep_kernel(
    const float* __restrict__ W1, const float* __restrict__ W2)
{
    int idx = blockIdx.x * 256 + threadIdx.x;   // 65536 total
    __nv_bfloat16 pp[3];
    if (idx < H * 2 * H) {                      // W1: [k=128][n=256]
        int k = idx >> 8;
        int n = idx & 255;
        split3(W1[idx], pp);
        int c = n >> 6, nl = n & 63;
        u32 off = swz256(nl, 2 * k);
        unsigned char* base = g_W1s + (size_t)c * 49152 + off;
        #pragma unroll
        for (int p = 0; p < 3; p++)
            *(__nv_bfloat16*)(base + p * 16384) = pp[p];
    } else {                                    // W2: [k2=256][n=128]
        int j  = idx - H * 2 * H;
        int k2 = j >> 7;
        int n  = j & 127;
        split3(W2[j], pp);
        int c = k2 >> 6, kl = k2 & 63;
        u32 off = swz128(n, 2 * kl);
        unsigned char* base = g_W2s + (size_t)c * 49152 + off;
        #pragma unroll
        for (int p = 0; p < 3; p++)
            *(__nv_bfloat16*)(base + p * 16384) = pp[p];
    }
}

// ---------------------------------------------------------------------------
// Prep2: split Wout (fp32 [H][V]) into 2 bf16 parts, transposed per 128-col
// chunk to [n][k] with swz256 rows. 16000 blocks x 256 = 4,096,000 elements.
// ---------------------------------------------------------------------------
__global__ void __launch_bounds__(256) prep2_kernel(const float* __restrict__ Wout)
{
    int idx = blockIdx.x * 256 + threadIdx.x;   // k*V + n, n fastest (coalesced)
    int k = idx / V;
    int n = idx - k * V;
    float x = Wout[idx];
    __nv_bfloat16 p0 = __float2bfloat16(x);
    __nv_bfloat16 p1 = __float2bfloat16(x - __bfloat162float(p0));
    int c  = n >> 7;
    int nl = n & 127;
    u32 off = swz256(nl, 2 * k);
    unsigned char* base = g_Wo + (size_t)c * 65536 + off;
    *(__nv_bfloat16*)(base)         = p0;
    *(__nv_bfloat16*)(base + 32768) = p1;
}

// Stage schedule: s = c*6 + g*3 + jj, W part j = 2-jj (smallest products first).
__device__ __forceinline__ const unsigned char* stage_src(int s) {
    int c = s / 6, g = (s / 3) % 2, jj = s % 3;
    int j = 2 - jj;
    return (g ? g_W2s : g_W1s) + (size_t)c * 49152 + (size_t)j * 16384;
}

// ---------------------------------------------------------------------------
// Encode: R10/R13 bitwise-proven configuration. UNCHANGED.
// SMEM (199168 B): E 3x32768 @0 | A2 3x16384 @98304 | W 3x16384 @147456
// ---------------------------------------------------------------------------
#define EO       0
#define EPART    32768
#define A2O      98304
#define A2PART   16384
#define WO       147456
#define CO       196608
#define ENC_SMEM 199168

__global__ void __launch_bounds__(256, 1) encode_mma_kernel(
    const int* __restrict__ seq, const float* __restrict__ embed,
    const float* __restrict__ b1, const float* __restrict__ b2,
    const float* __restrict__ gamma, const float* __restrict__ beta)
{
    extern __shared__ char smc[];
    const u32 sb = smem_u32(smc);
    float* b1s = (float*)(smc + CO);
    float* b2s = b1s + 256;
    float* gs  = b2s + 128;
    float* bs  = gs + 128;

    const int t    = threadIdx.x;
    const int lane = t & 31;
    const int w    = t >> 5;
    const int tile0 = blockIdx.x * TOK;

    {
        const unsigned char* src = stage_src(0) + t * 64;
        u32 dst = sb + WO + t * 64;
        cp16(dst, src); cp16(dst + 16, src + 16);
        cp16(dst + 32, src + 32); cp16(dst + 48, src + 48);
        asm volatile("cp.async.commit_group;");
    }

    b1s[t] = b1[t];
    if (t < 128) { b2s[t] = b2[t]; gs[t] = gamma[t]; bs[t] = beta[t]; }

    {
        int row = t >> 1, kh = t & 1;
        int tok = seq[tile0 + row];
        const float4* er = (const float4*)(embed + (size_t)tok * H) + kh * 16;
        #pragma unroll 4
        for (int i = 0; i < 16; i++) {
            float4 v = er[i];
            int col0 = kh * 64 + 4 * i;
            u32 offA = swz256(row, 2 * col0);
            __nv_bfloat16 px[3], py[3];
            split3(v.x, px); split3(v.y, py);
            #pragma unroll
            for (int p = 0; p < 3; p++)
                *(u32*)(smc + EO + p * EPART + offA) = pack_bf2(px[p], py[p]);
            split3(v.z, px); split3(v.w, py);
            #pragma unroll
            for (int p = 0; p < 3; p++)
                *(u32*)(smc + EO + p * EPART + offA + 4) = pack_bf2(px[p], py[p]);
        }
    }

    const int m0   = (w >> 1) * 32;
    const int n0g1 = (w & 1) * 32;
    const int n0g2 = (w & 1) * 64;
    const int lg   = lane >> 3;
    const int rsel = (lane & 7) + ((lg & 1) << 3);
    const int kbs  = (lg >> 1) << 4;
    const int frow = lane >> 2;
    const int fcol = 2 * (lane & 3);

    float c1[2][4][4];
    float c2[2][8][4];
    #pragma unroll
    for (int mt = 0; mt < 2; mt++)
        #pragma unroll
        for (int nt = 0; nt < 8; nt++)
            #pragma unroll
            for (int jj = 0; jj < 4; jj++) c2[mt][nt][jj] = 0.f;

    for (int s = 0; s < 24; s++) {
        const int jj  = s % 3;
        const int j   = 2 - jj;
        const int g   = (s / 3) % 2;
        const int buf = s % 3;

        if (s < 23) {
            const unsigned char* src = stage_src(s + 1) + t * 64;
            u32 dst = sb + WO + ((s + 1) % 3) * 16384 + t * 64;
            cp16(dst, src); cp16(dst + 16, src + 16);
            cp16(dst + 32, src + 32); cp16(dst + 48, src + 48);
            asm volatile("cp.async.commit_group;");
            asm volatile("cp.async.wait_group 1;");
        } else {
            asm volatile("cp.async.wait_group 0;");
        }
        __syncthreads();

        const u32 Bb = sb + WO + buf * 16384;

        if (g == 0) {
            if (jj == 0) {
                #pragma unroll
                for (int mt = 0; mt < 2; mt++)
                    #pragma unroll
                    for (int nt = 0; nt < 4; nt++)
                        #pragma unroll
                        for (int q = 0; q < 4; q++) c1[mt][nt][q] = 0.f;
            }
            for (int i = 2 - j; i >= 0; i--) {
                const u32 Ab = sb + EO + i * EPART;
                u32 af[2][2][4], qf[2][2][4];
                {
                    const int kb = 7 * 32 + kbs;
                    ldsm_x4(af[0][0], Ab + swz256(m0 + rsel, kb));
                    ldsm_x4(af[0][1], Ab + swz256(m0 + 16 + rsel, kb));
                    ldsm_x4(qf[0][0], Bb + swz256(n0g1 + rsel, kb));
                    ldsm_x4(qf[0][1], Bb + swz256(n0g1 + 16 + rsel, kb));
                }
                #pragma unroll
                for (int k16 = 7; k16 >= 0; k16--) {
                    const int cur = (7 - k16) & 1;
                    if (k16 > 0) {
                        const int kb2 = (k16 - 1) * 32 + kbs;
                        ldsm_x4(af[cur ^ 1][0], Ab + swz256(m0 + rsel, kb2));
                        ldsm_x4(af[cur ^ 1][1], Ab + swz256(m0 + 16 + rsel, kb2));
                        ldsm_x4(qf[cur ^ 1][0], Bb + swz256(n0g1 + rsel, kb2));
                        ldsm_x4(qf[cur ^ 1][1], Bb + swz256(n0g1 + 16 + rsel, kb2));
                    }
                    #pragma unroll
                    for (int mt = 0; mt < 2; mt++)
                        #pragma unroll
                        for (int nt = 0; nt < 4; nt++)
                            mma16816(c1[mt][nt], af[cur][mt],
                                     qf[cur][nt >> 1][nt & 1],
                                     qf[cur][nt >> 1][2 + (nt & 1)]);
                }
            }
            if (jj == 2) {
                const int c = s / 6;
                #pragma unroll
                for (int mt = 0; mt < 2; mt++) {
                    #pragma unroll
                    for (int nt = 0; nt < 4; nt++) {
                        int col = n0g1 + nt * 8 + fcol;
                        float bb0 = b1s[c * 64 + col];
                        float bb1 = b1s[c * 64 + col + 1];
                        #pragma unroll
                        for (int half = 0; half < 2; half++) {
                            int row = m0 + mt * 16 + frow + half * 8;
                            float h0 = fmaxf(c1[mt][nt][2 * half + 0] + bb0, 0.f);
                            float h1 = fmaxf(c1[mt][nt][2 * half + 1] + bb1, 0.f);
                            __nv_bfloat16 px[3], py[3];
                            split3(h0, px); split3(h1, py);
                            u32 off = swz128(row, 2 * col);
                            #pragma unroll
                            for (int p = 0; p < 3; p++)
                                *(u32*)(smc + A2O + p * A2PART + off) =
                                    pack_bf2(px[p], py[p]);
                        }
                    }
                }
            }
        } else {
            for (int i = 2 - j; i >= 0; i--) {
                const u32 Ab = sb + A2O + i * A2PART;
                u32 af[2][2][4], qf[2][4][4];
                {
                    const int kb = 3 * 32 + kbs;
                    ldsm_x4(af[0][0], Ab + swz128(m0 + rsel, kb));
                    ldsm_x4(af[0][1], Ab + swz128(m0 + 16 + rsel, kb));
                    #pragma unroll
                    for (int nt2 = 0; nt2 < 4; nt2++)
                        ldsm_x4(qf[0][nt2], Bb + swz128(n0g2 + nt2 * 16 + rsel, kb));
                }
                #pragma unroll
                for (int k16 = 3; k16 >= 0; k16--) {
                    const int cur = (3 - k16) & 1;
                    if (k16 > 0) {
                        const int kb2 = (k16 - 1) * 32 + kbs;
                        ldsm_x4(af[cur ^ 1][0], Ab + swz128(m0 + rsel, kb2));
                        ldsm_x4(af[cur ^ 1][1], Ab + swz128(m0 + 16 + rsel, kb2));
                        #pragma unroll
                        for (int nt2 = 0; nt2 < 4; nt2++)
                            ldsm_x4(qf[cur ^ 1][nt2],
                                    Bb + swz128(n0g2 + nt2 * 16 + rsel, kb2));
                    }
                    #pragma unroll
                    for (int mt = 0; mt < 2; mt++)
                        #pragma unroll
                        for (int nt = 0; nt < 8; nt++)
                            mma16816(c2[mt][nt], af[cur][mt],
                                     qf[cur][nt >> 1][nt & 1],
                                     qf[cur][nt >> 1][2 + (nt & 1)]);
                }
            }
        }
    }

    #pragma unroll
    for (int mt = 0; mt < 2; mt++) {
        #pragma unroll
        for (int nt = 0; nt < 8; nt++) {
            int col = n0g2 + nt * 8 + fcol;
            float bb0 = b2s[col], bb1 = b2s[col + 1];
            #pragma unroll
            for (int half = 0; half < 2; half++) {
                int row = m0 + mt * 16 + frow + half * 8;
                u32 off = swz256(row, 2 * col);
                float e0 = 0.f, e1 = 0.f;
                #pragma unroll
                for (int p = 2; p >= 0; p--) {
                    u32 ev = *(u32*)(smc + EO + p * EPART + off);
                    __nv_bfloat162 eb = *(__nv_bfloat162*)&ev;
                    e0 += __bfloat162float(eb.x);
                    e1 += __bfloat162float(eb.y);
                }
                c2[mt][nt][2 * half + 0] += bb0 + e0;
                c2[mt][nt][2 * half + 1] += bb1 + e1;
            }
        }
    }
    __syncthreads();

    float* ySM = (float*)(smc + EO);
    float* muS = (float*)(smc + A2O);
    float* ivS = muS + 128;
    #pragma unroll
    for (int mt = 0; mt < 2; mt++) {
        #pragma unroll
        for (int nt = 0; nt < 8; nt++) {
            int col = n0g2 + nt * 8 + fcol;
            #pragma unroll
            for (int half = 0; half < 2; half++) {
                int row = m0 + mt * 16 + frow + half * 8;
                *(float2*)(ySM + row * 132 + col) =
                    make_float2(c2[mt][nt][2 * half + 0], c2[mt][nt][2 * half + 1]);
            }
        }
    }
    __syncthreads();

    if (t < 128) {
        const float4* yr = (const float4*)(ySM + t * 132);
        float s = 0.f, q = 0.f;
        #pragma unroll 8
        for (int jj = 0; jj < 32; jj++) {
            float4 y = yr[jj];
            s += (y.x + y.y) + (y.z + y.w);
            q += y.x * y.x + y.y * y.y + y.z * y.z + y.w * y.w;
        }
        float mu  = s * (1.0f / H);
        float var = q * (1.0f / H) - mu * mu;
        muS[t] = mu;
        ivS[t] = rsqrtf(var + 1e-5f);
    }
    __syncthreads();

    #pragma unroll
    for (int i = t; i < 128 * 32; i += 256) {
        int row = i >> 5, jj = i & 31;
        float4 y = ((const float4*)(ySM + row * 132))[jj];
        float mu = muS[row], iv = ivS[row];
        float4 g4 = ((const float4*)gs)[jj];
        float4 b4 = ((const float4*)bs)[jj];
        float4 o4;
        o4.x = (y.x - mu) * iv * g4.x + b4.x;
        o4.y = (y.y - mu) * iv * g4.y + b4.y;
        o4.z = (y.z - mu) * iv * g4.z + b4.z;
        o4.w = (y.w - mu) * iv * g4.w + b4.w;
        ((float4*)(g_h + (size_t)(tile0 + row) * H))[jj] = o4;
    }
}

// ---------------------------------------------------------------------------
// Scan (bitwise-proven) + fused rp epilogue. UNCHANGED from R13.
// ---------------------------------------------------------------------------
__global__ void __launch_bounds__(128, 2) scan_kernel(
    const float* __restrict__ Wrp, const float* __restrict__ brp)
{
    const int b = blockIdx.x;
    const int tid = threadIdx.x;
    const int lane = tid & 31;
    const int wid = tid >> 5;

    __shared__ float ks[2][H];
    __shared__ float red_kk[4];
    __shared__ float red_ee[4];

    float2 Mr[64];
    #pragma unroll
    for (int q = 0; q < 64; q++) Mr[q] = make_float2(0.f, 0.f);

    const float* hb = g_h + (size_t)b * L * H;
    float kv_next = hb[tid];

    for (int t = 0; t < L - 1; t++) {
        const int buf = t & 1;
        const float kv = kv_next;
        ks[buf][tid] = kv;

        float p = kv * kv;
        #pragma unroll
        for (int o = 16; o; o >>= 1) p += __shfl_xor_sync(0xffffffffu, p, o);
        if (lane == 0) red_kk[wid] = p;
        __syncthreads();

        kv_next = hb[(size_t)(t + 1) * H + tid];
        const float kk = (red_kk[0] + red_kk[1]) + (red_kk[2] + red_kk[3]);

        const float4* k4 = (const float4*)ks[buf];
        float2 a0 = make_float2(0.f, 0.f), a1 = a0, a2 = a0, a3 = a0;
        #pragma unroll
        for (int q = 0; q < 32; q += 2) {
            float4 ka = k4[q];
            float4 kb = k4[q + 1];
            const float2* kap = reinterpret_cast<const float2*>(&ka);
            const float2* kbp = reinterpret_cast<const float2*>(&kb);
            a0 = ffma2(Mr[2 * q + 0], kap[0], a0);
            a1 = ffma2(Mr[2 * q + 1], kap[1], a1);
            a2 = ffma2(Mr[2 * q + 2], kbp[0], a2);
            a3 = ffma2(Mr[2 * q + 3], kbp[1], a3);
        }
        const float vp = ((a0.x + a0.y) + (a1.x + a1.y))
                       + ((a2.x + a2.y) + (a3.x + a3.y));
        const float err = kv - vp / (kk + 1e-6f);

        float pe = err * err;
        #pragma unroll
        for (int o = 16; o; o >>= 1) pe += __shfl_xor_sync(0xffffffffu, pe, o);
        if (lane == 0) red_ee[wid] = pe;
        __syncthreads();
        const float ee = (red_ee[0] + red_ee[1]) + (red_ee[2] + red_ee[3]);

        if (ee > 0.16f * kk) {
            const float2 e2 = make_float2(err, err);
            #pragma unroll
            for (int q = 0; q < 32; q++) {
                float4 kq = k4[q];
                const float2* kp = reinterpret_cast<const float2*>(&kq);
                Mr[2 * q + 0] = ffma2(e2, kp[0], Mr[2 * q + 0]);
                Mr[2 * q + 1] = ffma2(e2, kp[1], Mr[2 * q + 1]);
            }
        }
    }

    ks[1][tid] = kv_next;
    __syncthreads();
    const float4* k4 = (const float4*)ks[1];
    float2 a0 = make_float2(0.f, 0.f), a1 = a0, a2 = a0, a3 = a0;
    #pragma unroll
    for (int q = 0; q < 32; q += 2) {
        float4 ka = k4[q];
        float4 kb = k4[q + 1];
        const float2* kap = reinterpret_cast<const float2*>(&ka);
        const float2* kbp = reinterpret_cast<const float2*>(&kb);
        a0 = ffma2(Mr[2 * q + 0], kap[0], a0);
        a1 = ffma2(Mr[2 * q + 1], kap[1], a1);
        a2 = ffma2(Mr[2 * q + 2], kbp[0], a2);
        a3 = ffma2(Mr[2 * q + 3], kbp[1], a3);
    }
    const float rv = ((a0.x + a0.y) + (a1.x + a1.y))
                   + ((a2.x + a2.y) + (a3.x + a3.y));

    __syncthreads();
    ks[0][tid] = rv;
    __syncthreads();
    float acc = brp[tid];
    #pragma unroll 8
    for (int j = 0; j < H; j++) acc += ks[0][j] * Wrp[j * H + tid];
    g_rp[b * H + tid] = acc;
}

// ---------------------------------------------------------------------------
// out = rp @ Wout + bout via 3-pass bf16x2 mma (no gates downstream; error
// ~3e-5 << 1e-3). Grid (250 vocab chunks, 4 batch quads), 256 threads.
// SMEM (98304): rp parts 2x16384 @0 | Wo double buffer 2x32768 @32768
// ---------------------------------------------------------------------------
#define ORP    0
#define OWO    32768
#define OUT_SMEM 98304

__global__ void __launch_bounds__(256) out_mma_kernel(
    const float* __restrict__ bout, float* __restrict__ out)
{
    extern __shared__ char smc[];
    const u32 sb = smem_u32(smc);
    const int t    = threadIdx.x;
    const int lane = t & 31;
    const int w    = t >> 5;
    const int chunk = blockIdx.x;          // 0..249
    const int b0    = blockIdx.y * 64;     // batch base
    const int v0    = chunk * 128;         // vocab base

    // Stage 0: async-load Wo part0 for this chunk (32768 B, 128 B/thread).
    {
        const unsigned char* src = g_Wo + (size_t)chunk * 65536 + t * 128;
        u32 dst = sb + OWO + t * 128;
        #pragma unroll
        for (int i = 0; i < 8; i++) cp16(dst + 16 * i, src + 16 * i);
        asm volatile("cp.async.commit_group;");
    }
    // Prefetch part1 into the second buffer.
    {
        const unsigned char* src = g_Wo + (size_t)chunk * 65536 + 32768 + t * 128;
        u32 dst = sb + OWO + 32768 + t * 128;
        #pragma unroll
        for (int i = 0; i < 8; i++) cp16(dst + 16 * i, src + 16 * i);
        asm volatile("cp.async.commit_group;");
    }

    // Load rp[64 x 128] and split2 into SMEM parts (swz256 rows).
    {
        int row = t >> 2, kq = (t & 3) * 32;
        const float4* rr = (const float4*)(g_rp + (size_t)(b0 + row) * H + kq);
        #pragma unroll
        for (int i = 0; i < 8; i++) {
            float4 v = rr[i];
            int col0 = kq + 4 * i;
            u32 off = swz256(row, 2 * col0);
            __nv_bfloat16 x0, x1, y0, y1;
            x0 = __float2bfloat16(v.x); x1 = __float2bfloat16(v.x - __bfloat162float(x0));
            y0 = __float2bfloat16(v.y); y1 = __float2bfloat16(v.y - __bfloat162float(y0));
            *(u32*)(smc + ORP + off)         = pack_bf2(x0, y0);
            *(u32*)(smc + ORP + 16384 + off) = pack_bf2(x1, y1);
            x0 = __float2bfloat16(v.z); x1 = __float2bfloat16(v.z - __bfloat162float(x0));
            y0 = __float2bfloat16(v.w); y1 = __float2bfloat16(v.w - __bfloat162float(y0));
            *(u32*)(smc + ORP + off + 4)         = pack_bf2(x0, y0);
            *(u32*)(smc + ORP + 16384 + off + 4) = pack_bf2(x1, y1);
        }
    }
    asm volatile("cp.async.wait_group 1;");   // part0 resident
    __syncthreads();                          // rp parts + Wo part0 visible

    const int m0   = (w >> 1) * 16;           // 4 m-groups of 16 batches
    const int n0   = (w & 1) * 64;            // 2 n-groups of 64 vocab
    const int lg   = lane >> 3;
    const int rsel = (lane & 7) + ((lg & 1) << 3);
    const int kbs  = (lg >> 1) << 4;
    const int frow = lane >> 2;
    const int fcol = 2 * (lane & 3);

    float acc[8][4];
    #pragma unroll
    for (int nt = 0; nt < 8; nt++)
        #pragma unroll
        for (int q = 0; q < 4; q++) acc[nt][q] = 0.f;

    // Pass order: (rp1 x w0), (rp0 x w0) on buf0; then (rp0 x w1).
    const int passA[3] = {1, 0, 0};
    const int passW[3] = {0, 0, 1};
    #pragma unroll
    for (int pp = 0; pp < 3; pp++) {
        if (pp == 2) {
            asm volatile("cp.async.wait_group 0;");   // part1 resident
            __syncthreads();
        }
        const u32 Ab = sb + ORP + passA[pp] * 16384;
        const u32 Bb = sb + OWO + passW[pp] * 32768;
        #pragma unroll
        for (int k16 = 0; k16 < 8; k16++) {
            const int kb = k16 * 32 + kbs;
            u32 a[4], q[4][4];
            ldsm_x4(a, Ab + swz256(m0 + rsel, kb));
            #pragma unroll
            for (int nt2 = 0; nt2 < 4; nt2++)
                ldsm_x4(q[nt2], Bb + swz256(n0 + nt2 * 16 + rsel, kb));
            #pragma unroll
            for (int nt = 0; nt < 8; nt++)
                mma16816(acc[nt], a, q[nt >> 1][nt & 1], q[nt >> 1][2 + (nt & 1)]);
        }
    }

    // Epilogue: + bout, store fp32.
    #pragma unroll
    for (int nt = 0; nt < 8; nt++) {
        int col = v0 + n0 + nt * 8 + fcol;
        float bo0 = bout[col], bo1 = bout[col + 1];
        #pragma unroll
        for (int half = 0; half < 2; half++) {
            int row = b0 + m0 + frow + half * 8;
            float2 o2 = make_float2(acc[nt][2 * half + 0] + bo0,
                                    acc[nt][2 * half + 1] + bo1);
            *(float2*)(out + (size_t)row * V + col) = o2;
        }
    }
}

// ---------------------------------------------------------------------------
extern "C" void kernel_launch(void* const* d_in, const int* in_sizes, int n_in,
                              void* d_out, int out_size)
{
    const int*   seq   = (const int*)  d_in[0];
    const float* embed = (const float*)d_in[1];
    const float* W1    = (const float*)d_in[2];
    const float* b1    = (const float*)d_in[3];
    const float* W2    = (const float*)d_in[4];
    const float* b2    = (const float*)d_in[5];
    const float* gamma = (const float*)d_in[6];
    const float* beta  = (const float*)d_in[7];
    const float* Wrp   = (const float*)d_in[8];
    const float* brp   = (const float*)d_in[9];
    const float* Wout  = (const float*)d_in[10];
    const float* bout  = (const float*)d_in[11];
    float* out = (float*)d_out;

    cudaFuncSetAttribute(encode_mma_kernel,
                         cudaFuncAttributeMaxDynamicSharedMemorySize, ENC_SMEM);
    cudaFuncSetAttribute(out_mma_kernel,
                         cudaFuncAttributeMaxDynamicSharedMemorySize, OUT_SMEM);

    prep_kernel<<<256, 256>>>(W1, W2);
    prep2_kernel<<<16000, 256>>>(Wout);
    encode_mma_kernel<<<BL / TOK, 256, ENC_SMEM>>>(seq, embed, b1, b2, gamma, beta);
    scan_kernel<<<B, 128>>>(Wrp, brp);
    dim3 og(250, 4);
    out_mma_kernel<<<og, 256, OUT_SMEM>>>(bout, out);
}

// round 15
// speedup vs baseline: 1.0069x; 1.0069x over previous
#include <cuda_runtime.h>
#include <cuda_bf16.h>
#include <cstdint>
#include <cstddef>

#define B 256
#define L 2048
#define H 128
#define V 32000
#define BL (B * L)
#define TOK 128

typedef unsigned long long u64;
typedef uint32_t u32;

// ---------------------------------------------------------------------------
// helpers
// ---------------------------------------------------------------------------
__device__ __forceinline__ u32 smem_u32(const void* p) {
    return (u32)__cvta_generic_to_shared(p);
}

__device__ __forceinline__ void ldsm_x4(u32* r, u32 addr) {
    asm volatile("ldmatrix.sync.aligned.m8n8.x4.shared.b16 {%0,%1,%2,%3}, [%4];"
                 : "=r"(r[0]), "=r"(r[1]), "=r"(r[2]), "=r"(r[3]) : "r"(addr));
}

__device__ __forceinline__ void mma16816(float* d, const u32* a, u32 b0, u32 b1) {
    asm volatile(
        "mma.sync.aligned.m16n8k16.row.col.f32.bf16.bf16.f32 "
        "{%0,%1,%2,%3}, {%4,%5,%6,%7}, {%8,%9}, {%0,%1,%2,%3};"
        : "+f"(d[0]), "+f"(d[1]), "+f"(d[2]), "+f"(d[3])
        : "r"(a[0]), "r"(a[1]), "r"(a[2]), "r"(a[3]), "r"(b0), "r"(b1));
}

__device__ __forceinline__ void cp16(u32 dst, const void* src) {
    asm volatile("cp.async.cg.shared.global [%0], [%1], 16;" :: "r"(dst), "l"(src));
}

// Packed dual-FMA (scan kernel).
__device__ __forceinline__ float2 ffma2(float2 a, float2 b, float2 c) {
    float2 d;
    asm("fma.rn.f32x2 %0, %1, %2, %3;"
        : "=l"(*(u64*)&d)
        : "l"(*(u64*)&a), "l"(*(u64*)&b), "l"(*(u64*)&c));
    return d;
}

// 3-way bf16 split: x = a0+a1+a2 + O(2^-27 * x)
__device__ __forceinline__ void split3(float x, __nv_bfloat16* a) {
    a[0] = __float2bfloat16(x);
    float r = x - __bfloat162float(a[0]);
    a[1] = __float2bfloat16(r);  r -= __bfloat162float(a[1]);
    a[2] = __float2bfloat16(r);
}
__device__ __forceinline__ u32 pack_bf2(__nv_bfloat16 lo, __nv_bfloat16 hi) {
    __nv_bfloat162 p;
    p.x = lo; p.y = hi;
    return *(u32*)&p;
}

// XOR chunk swizzles: conflict-free ldmatrix on natural row strides.
__device__ __forceinline__ u32 swz256(int row, int kb) {
    return (u32)(row * 256 + ((((kb >> 4) ^ (row & 7)) << 4) | (kb & 15)));
}
__device__ __forceinline__ u32 swz128(int row, int kb) {
    return (u32)(row * 128 + ((((kb >> 4) ^ (row & 7)) << 4) | (kb & 15)));
}

// ---------------------------------------------------------------------------
// Scratch device globals.
// ---------------------------------------------------------------------------
__device__ float g_h[(size_t)BL * H];
__device__ float g_rp[B * H];
// Pre-split, pre-swizzled weight part-tiles (3 parts):
__device__ unsigned char g_W1s[4 * 3 * 16384];
__device__ unsigned char g_W2s[4 * 3 * 16384];
// Wout split (2 bf16 parts), chunked by 128 vocab cols:
// g_Wo: [chunk=250][part=2][128 n-rows x 128 k bf16, swz256 rows] = 16.384 MB
__device__ unsigned char g_Wo[250 * 2 * 32768];

// ---------------------------------------------------------------------------
// Prep: split3 + transpose + swizzle W1/W2.
// ---------------------------------------------------------------------------
__global__ void __launch_bounds__(256) prep_kernel(
    const float* __restrict__ W1, const float* __restrict__ W2)
{
    int idx = blockIdx.x * 256 + threadIdx.x;   // 65536 total
    __nv_bfloat16 pp[3];
    if (idx < H * 2 * H) {                      // W1: [k=128][n=256]
        int k = idx >> 8;
        int n = idx & 255;
        split3(W1[idx], pp);
        int c = n >> 6, nl = n & 63;
        u32 off = swz256(nl, 2 * k);
        unsigned char* base = g_W1s + (size_t)c * 49152 + off;
        #pragma unroll
        for (int p = 0; p < 3; p++)
            *(__nv_bfloat16*)(base + p * 16384) = pp[p];
    } else {                                    // W2: [k2=256][n=128]
        int j  = idx - H * 2 * H;
        int k2 = j >> 7;
        int n  = j & 127;
        split3(W2[j], pp);
        int c = k2 >> 6, kl = k2 & 63;
        u32 off = swz128(n, 2 * kl);
        unsigned char* base = g_W2s + (size_t)c * 49152 + off;
        #pragma unroll
        for (int p = 0; p < 3; p++)
            *(__nv_bfloat16*)(base + p * 16384) = pp[p];
    }
}

// ---------------------------------------------------------------------------
// Prep2 v2: split Wout into 2 bf16 part-tiles via SMEM-staged transpose.
// One CTA per 128-col vocab chunk (grid 250, 256 threads).
// Phase 1: coalesced float4 loads of [128k][128n] tile -> SMEM [128][132] fp32.
// Phase 2: per-n-row transpose reads (conflict-free down k), split2, u32
//          writes into the swizzled [n][k] images out_mma consumes.
// ---------------------------------------------------------------------------
#define P2_STR  132
#define P2_SMEM (128 * P2_STR * 4)   // 67584

__global__ void __launch_bounds__(256) prep2_kernel(const float* __restrict__ Wout)
{
    extern __shared__ float sw[];    // [128][P2_STR]
    const int c  = blockIdx.x;
    const int v0 = c * 128;
    const int t  = threadIdx.x;

    // Phase 1: 4096 float4 loads (16 per thread), coalesced along n.
    #pragma unroll
    for (int i = 0; i < 16; i++) {
        int idx = t + 256 * i;           // 0..4095
        int row = idx >> 5;              // k index (32 float4 per row)
        int c4  = idx & 31;
        float4 v = *(const float4*)(Wout + (size_t)row * V + v0 + c4 * 4);
        float* d = sw + row * P2_STR + c4 * 4;
        *(float4*)d = v;
    }
    __syncthreads();

    // Phase 2: thread owns n-row nl, k-half kh; write u32 (2 adjacent k).
    const int nl = t >> 1;
    const int kh = (t & 1) * 64;
    unsigned char* base = g_Wo + (size_t)c * 65536;
    #pragma unroll 8
    for (int k = kh; k < kh + 64; k += 2) {
        float x0 = sw[k * P2_STR + nl];
        float x1 = sw[(k + 1) * P2_STR + nl];
        __nv_bfloat16 a0 = __float2bfloat16(x0);
        __nv_bfloat16 a1 = __float2bfloat16(x0 - __bfloat162float(a0));
        __nv_bfloat16 b0 = __float2bfloat16(x1);
        __nv_bfloat16 b1 = __float2bfloat16(x1 - __bfloat162float(b0));
        u32 off = swz256(nl, 2 * k);     // 2k%16 in {0,4,8,12}: u32 covers k,k+1
        *(u32*)(base + off)         = pack_bf2(a0, b0);
        *(u32*)(base + 32768 + off) = pack_bf2(a1, b1);
    }
}

// Stage schedule: s = c*6 + g*3 + jj, W part j = 2-jj (smallest products first).
__device__ __forceinline__ const unsigned char* stage_src(int s) {
    int c = s / 6, g = (s / 3) % 2, jj = s % 3;
    int j = 2 - jj;
    return (g ? g_W2s : g_W1s) + (size_t)c * 49152 + (size_t)j * 16384;
}

// ---------------------------------------------------------------------------
// Encode: R10/R13 bitwise-proven configuration. UNCHANGED.
// SMEM (199168 B): E 3x32768 @0 | A2 3x16384 @98304 | W 3x16384 @147456
// ---------------------------------------------------------------------------
#define EO       0
#define EPART    32768
#define A2O      98304
#define A2PART   16384
#define WO       147456
#define CO       196608
#define ENC_SMEM 199168

__global__ void __launch_bounds__(256, 1) encode_mma_kernel(
    const int* __restrict__ seq, const float* __restrict__ embed,
    const float* __restrict__ b1, const float* __restrict__ b2,
    const float* __restrict__ gamma, const float* __restrict__ beta)
{
    extern __shared__ char smc[];
    const u32 sb = smem_u32(smc);
    float* b1s = (float*)(smc + CO);
    float* b2s = b1s + 256;
    float* gs  = b2s + 128;
    float* bs  = gs + 128;

    const int t    = threadIdx.x;
    const int lane = t & 31;
    const int w    = t >> 5;
    const int tile0 = blockIdx.x * TOK;

    {
        const unsigned char* src = stage_src(0) + t * 64;
        u32 dst = sb + WO + t * 64;
        cp16(dst, src); cp16(dst + 16, src + 16);
        cp16(dst + 32, src + 32); cp16(dst + 48, src + 48);
        asm volatile("cp.async.commit_group;");
    }

    b1s[t] = b1[t];
    if (t < 128) { b2s[t] = b2[t]; gs[t] = gamma[t]; bs[t] = beta[t]; }

    {
        int row = t >> 1, kh = t & 1;
        int tok = seq[tile0 + row];
        const float4* er = (const float4*)(embed + (size_t)tok * H) + kh * 16;
        #pragma unroll 4
        for (int i = 0; i < 16; i++) {
            float4 v = er[i];
            int col0 = kh * 64 + 4 * i;
            u32 offA = swz256(row, 2 * col0);
            __nv_bfloat16 px[3], py[3];
            split3(v.x, px); split3(v.y, py);
            #pragma unroll
            for (int p = 0; p < 3; p++)
                *(u32*)(smc + EO + p * EPART + offA) = pack_bf2(px[p], py[p]);
            split3(v.z, px); split3(v.w, py);
            #pragma unroll
            for (int p = 0; p < 3; p++)
                *(u32*)(smc + EO + p * EPART + offA + 4) = pack_bf2(px[p], py[p]);
        }
    }

    const int m0   = (w >> 1) * 32;
    const int n0g1 = (w & 1) * 32;
    const int n0g2 = (w & 1) * 64;
    const int lg   = lane >> 3;
    const int rsel = (lane & 7) + ((lg & 1) << 3);
    const int kbs  = (lg >> 1) << 4;
    const int frow = lane >> 2;
    const int fcol = 2 * (lane & 3);

    float c1[2][4][4];
    float c2[2][8][4];
    #pragma unroll
    for (int mt = 0; mt < 2; mt++)
        #pragma unroll
        for (int nt = 0; nt < 8; nt++)
            #pragma unroll
            for (int jj = 0; jj < 4; jj++) c2[mt][nt][jj] = 0.f;

    for (int s = 0; s < 24; s++) {
        const int jj  = s % 3;
        const int j   = 2 - jj;
        const int g   = (s / 3) % 2;
        const int buf = s % 3;

        if (s < 23) {
            const unsigned char* src = stage_src(s + 1) + t * 64;
            u32 dst = sb + WO + ((s + 1) % 3) * 16384 + t * 64;
            cp16(dst, src); cp16(dst + 16, src + 16);
            cp16(dst + 32, src + 32); cp16(dst + 48, src + 48);
            asm volatile("cp.async.commit_group;");
            asm volatile("cp.async.wait_group 1;");
        } else {
            asm volatile("cp.async.wait_group 0;");
        }
        __syncthreads();

        const u32 Bb = sb + WO + buf * 16384;

        if (g == 0) {
            if (jj == 0) {
                #pragma unroll
                for (int mt = 0; mt < 2; mt++)
                    #pragma unroll
                    for (int nt = 0; nt < 4; nt++)
                        #pragma unroll
                        for (int q = 0; q < 4; q++) c1[mt][nt][q] = 0.f;
            }
            for (int i = 2 - j; i >= 0; i--) {
                const u32 Ab = sb + EO + i * EPART;
                u32 af[2][2][4], qf[2][2][4];
                {
                    const int kb = 7 * 32 + kbs;
                    ldsm_x4(af[0][0], Ab + swz256(m0 + rsel, kb));
                    ldsm_x4(af[0][1], Ab + swz256(m0 + 16 + rsel, kb));
                    ldsm_x4(qf[0][0], Bb + swz256(n0g1 + rsel, kb));
                    ldsm_x4(qf[0][1], Bb + swz256(n0g1 + 16 + rsel, kb));
                }
                #pragma unroll
                for (int k16 = 7; k16 >= 0; k16--) {
                    const int cur = (7 - k16) & 1;
                    if (k16 > 0) {
                        const int kb2 = (k16 - 1) * 32 + kbs;
                        ldsm_x4(af[cur ^ 1][0], Ab + swz256(m0 + rsel, kb2));
                        ldsm_x4(af[cur ^ 1][1], Ab + swz256(m0 + 16 + rsel, kb2));
                        ldsm_x4(qf[cur ^ 1][0], Bb + swz256(n0g1 + rsel, kb2));
                        ldsm_x4(qf[cur ^ 1][1], Bb + swz256(n0g1 + 16 + rsel, kb2));
                    }
                    #pragma unroll
                    for (int mt = 0; mt < 2; mt++)
                        #pragma unroll
                        for (int nt = 0; nt < 4; nt++)
                            mma16816(c1[mt][nt], af[cur][mt],
                                     qf[cur][nt >> 1][nt & 1],
                                     qf[cur][nt >> 1][2 + (nt & 1)]);
                }
            }
            if (jj == 2) {
                const int c = s / 6;
                #pragma unroll
                for (int mt = 0; mt < 2; mt++) {
                    #pragma unroll
                    for (int nt = 0; nt < 4; nt++) {
                        int col = n0g1 + nt * 8 + fcol;
                        float bb0 = b1s[c * 64 + col];
                        float bb1 = b1s[c * 64 + col + 1];
                        #pragma unroll
                        for (int half = 0; half < 2; half++) {
                            int row = m0 + mt * 16 + frow + half * 8;
                            float h0 = fmaxf(c1[mt][nt][2 * half + 0] + bb0, 0.f);
                            float h1 = fmaxf(c1[mt][nt][2 * half + 1] + bb1, 0.f);
                            __nv_bfloat16 px[3], py[3];
                            split3(h0, px); split3(h1, py);
                            u32 off = swz128(row, 2 * col);
                            #pragma unroll
                            for (int p = 0; p < 3; p++)
                                *(u32*)(smc + A2O + p * A2PART + off) =
                                    pack_bf2(px[p], py[p]);
                        }
                    }
                }
            }
        } else {
            for (int i = 2 - j; i >= 0; i--) {
                const u32 Ab = sb + A2O + i * A2PART;
                u32 af[2][2][4], qf[2][4][4];
                {
                    const int kb = 3 * 32 + kbs;
                    ldsm_x4(af[0][0], Ab + swz128(m0 + rsel, kb));
                    ldsm_x4(af[0][1], Ab + swz128(m0 + 16 + rsel, kb));
                    #pragma unroll
                    for (int nt2 = 0; nt2 < 4; nt2++)
                        ldsm_x4(qf[0][nt2], Bb + swz128(n0g2 + nt2 * 16 + rsel, kb));
                }
                #pragma unroll
                for (int k16 = 3; k16 >= 0; k16--) {
                    const int cur = (3 - k16) & 1;
                    if (k16 > 0) {
                        const int kb2 = (k16 - 1) * 32 + kbs;
                        ldsm_x4(af[cur ^ 1][0], Ab + swz128(m0 + rsel, kb2));
                        ldsm_x4(af[cur ^ 1][1], Ab + swz128(m0 + 16 + rsel, kb2));
                        #pragma unroll
                        for (int nt2 = 0; nt2 < 4; nt2++)
                            ldsm_x4(qf[cur ^ 1][nt2],
                                    Bb + swz128(n0g2 + nt2 * 16 + rsel, kb2));
                    }
                    #pragma unroll
                    for (int mt = 0; mt < 2; mt++)
                        #pragma unroll
                        for (int nt = 0; nt < 8; nt++)
                            mma16816(c2[mt][nt], af[cur][mt],
                                     qf[cur][nt >> 1][nt & 1],
                                     qf[cur][nt >> 1][2 + (nt & 1)]);
                }
            }
        }
    }

    #pragma unroll
    for (int mt = 0; mt < 2; mt++) {
        #pragma unroll
        for (int nt = 0; nt < 8; nt++) {
            int col = n0g2 + nt * 8 + fcol;
            float bb0 = b2s[col], bb1 = b2s[col + 1];
            #pragma unroll
            for (int half = 0; half < 2; half++) {
                int row = m0 + mt * 16 + frow + half * 8;
                u32 off = swz256(row, 2 * col);
                float e0 = 0.f, e1 = 0.f;
                #pragma unroll
                for (int p = 2; p >= 0; p--) {
                    u32 ev = *(u32*)(smc + EO + p * EPART + off);
                    __nv_bfloat162 eb = *(__nv_bfloat162*)&ev;
                    e0 += __bfloat162float(eb.x);
                    e1 += __bfloat162float(eb.y);
                }
                c2[mt][nt][2 * half + 0] += bb0 + e0;
                c2[mt][nt][2 * half + 1] += bb1 + e1;
            }
        }
    }
    __syncthreads();

    float* ySM = (float*)(smc + EO);
    float* muS = (float*)(smc + A2O);
    float* ivS = muS + 128;
    #pragma unroll
    for (int mt = 0; mt < 2; mt++) {
        #pragma unroll
        for (int nt = 0; nt < 8; nt++) {
            int col = n0g2 + nt * 8 + fcol;
            #pragma unroll
            for (int half = 0; half < 2; half++) {
                int row = m0 + mt * 16 + frow + half * 8;
                *(float2*)(ySM + row * 132 + col) =
                    make_float2(c2[mt][nt][2 * half + 0], c2[mt][nt][2 * half + 1]);
            }
        }
    }
    __syncthreads();

    if (t < 128) {
        const float4* yr = (const float4*)(ySM + t * 132);
        float s = 0.f, q = 0.f;
        #pragma unroll 8
        for (int jj = 0; jj < 32; jj++) {
            float4 y = yr[jj];
            s += (y.x + y.y) + (y.z + y.w);
            q += y.x * y.x + y.y * y.y + y.z * y.z + y.w * y.w;
        }
        float mu  = s * (1.0f / H);
        float var = q * (1.0f / H) - mu * mu;
        muS[t] = mu;
        ivS[t] = rsqrtf(var + 1e-5f);
    }
    __syncthreads();

    #pragma unroll
    for (int i = t; i < 128 * 32; i += 256) {
        int row = i >> 5, jj = i & 31;
        float4 y = ((const float4*)(ySM + row * 132))[jj];
        float mu = muS[row], iv = ivS[row];
        float4 g4 = ((const float4*)gs)[jj];
        float4 b4 = ((const float4*)bs)[jj];
        float4 o4;
        o4.x = (y.x - mu) * iv * g4.x + b4.x;
        o4.y = (y.y - mu) * iv * g4.y + b4.y;
        o4.z = (y.z - mu) * iv * g4.z + b4.z;
        o4.w = (y.w - mu) * iv * g4.w + b4.w;
        ((float4*)(g_h + (size_t)(tile0 + row) * H))[jj] = o4;
    }
}

// ---------------------------------------------------------------------------
// Scan (bitwise-proven) + fused rp epilogue. UNCHANGED.
// ---------------------------------------------------------------------------
__global__ void __launch_bounds__(128, 2) scan_kernel(
    const float* __restrict__ Wrp, const float* __restrict__ brp)
{
    const int b = blockIdx.x;
    const int tid = threadIdx.x;
    const int lane = tid & 31;
    const int wid = tid >> 5;

    __shared__ float ks[2][H];
    __shared__ float red_kk[4];
    __shared__ float red_ee[4];

    float2 Mr[64];
    #pragma unroll
    for (int q = 0; q < 64; q++) Mr[q] = make_float2(0.f, 0.f);

    const float* hb = g_h + (size_t)b * L * H;
    float kv_next = hb[tid];

    for (int t = 0; t < L - 1; t++) {
        const int buf = t & 1;
        const float kv = kv_next;
        ks[buf][tid] = kv;

        float p = kv * kv;
        #pragma unroll
        for (int o = 16; o; o >>= 1) p += __shfl_xor_sync(0xffffffffu, p, o);
        if (lane == 0) red_kk[wid] = p;
        __syncthreads();

        kv_next = hb[(size_t)(t + 1) * H + tid];
        const float kk = (red_kk[0] + red_kk[1]) + (red_kk[2] + red_kk[3]);

        const float4* k4 = (const float4*)ks[buf];
        float2 a0 = make_float2(0.f, 0.f), a1 = a0, a2 = a0, a3 = a0;
        #pragma unroll
        for (int q = 0; q < 32; q += 2) {
            float4 ka = k4[q];
            float4 kb = k4[q + 1];
            const float2* kap = reinterpret_cast<const float2*>(&ka);
            const float2* kbp = reinterpret_cast<const float2*>(&kb);
            a0 = ffma2(Mr[2 * q + 0], kap[0], a0);
            a1 = ffma2(Mr[2 * q + 1], kap[1], a1);
            a2 = ffma2(Mr[2 * q + 2], kbp[0], a2);
            a3 = ffma2(Mr[2 * q + 3], kbp[1], a3);
        }
        const float vp = ((a0.x + a0.y) + (a1.x + a1.y))
                       + ((a2.x + a2.y) + (a3.x + a3.y));
        const float err = kv - vp / (kk + 1e-6f);

        float pe = err * err;
        #pragma unroll
        for (int o = 16; o; o >>= 1) pe += __shfl_xor_sync(0xffffffffu, pe, o);
        if (lane == 0) red_ee[wid] = pe;
        __syncthreads();
        const float ee = (red_ee[0] + red_ee[1]) + (red_ee[2] + red_ee[3]);

        if (ee > 0.16f * kk) {
            const float2 e2 = make_float2(err, err);
            #pragma unroll
            for (int q = 0; q < 32; q++) {
                float4 kq = k4[q];
                const float2* kp = reinterpret_cast<const float2*>(&kq);
                Mr[2 * q + 0] = ffma2(e2, kp[0], Mr[2 * q + 0]);
                Mr[2 * q + 1] = ffma2(e2, kp[1], Mr[2 * q + 1]);
            }
        }
    }

    ks[1][tid] = kv_next;
    __syncthreads();
    const float4* k4 = (const float4*)ks[1];
    float2 a0 = make_float2(0.f, 0.f), a1 = a0, a2 = a0, a3 = a0;
    #pragma unroll
    for (int q = 0; q < 32; q += 2) {
        float4 ka = k4[q];
        float4 kb = k4[q + 1];
        const float2* kap = reinterpret_cast<const float2*>(&ka);
        const float2* kbp = reinterpret_cast<const float2*>(&kb);
        a0 = ffma2(Mr[2 * q + 0], kap[0], a0);
        a1 = ffma2(Mr[2 * q + 1], kap[1], a1);
        a2 = ffma2(Mr[2 * q + 2], kbp[0], a2);
        a3 = ffma2(Mr[2 * q + 3], kbp[1], a3);
    }
    const float rv = ((a0.x + a0.y) + (a1.x + a1.y))
                   + ((a2.x + a2.y) + (a3.x + a3.y));

    __syncthreads();
    ks[0][tid] = rv;
    __syncthreads();
    float acc = brp[tid];
    #pragma unroll 8
    for (int j = 0; j < H; j++) acc += ks[0][j] * Wrp[j * H + tid];
    g_rp[b * H + tid] = acc;
}

// ---------------------------------------------------------------------------
// out = rp @ Wout + bout via 3-pass bf16x2 mma. UNCHANGED from R14.
// SMEM (98304): rp parts 2x16384 @0 | Wo double buffer 2x32768 @32768
// ---------------------------------------------------------------------------
#define ORP    0
#define OWO    32768
#define OUT_SMEM 98304

__global__ void __launch_bounds__(256) out_mma_kernel(
    const float* __restrict__ bout, float* __restrict__ out)
{
    extern __shared__ char smc[];
    const u32 sb = smem_u32(smc);
    const int t    = threadIdx.x;
    const int lane = t & 31;
    const int w    = t >> 5;
    const int chunk = blockIdx.x;          // 0..249
    const int b0    = blockIdx.y * 64;     // batch base
    const int v0    = chunk * 128;         // vocab base

    {
        const unsigned char* src = g_Wo + (size_t)chunk * 65536 + t * 128;
        u32 dst = sb + OWO + t * 128;
        #pragma unroll
        for (int i = 0; i < 8; i++) cp16(dst + 16 * i, src + 16 * i);
        asm volatile("cp.async.commit_group;");
    }
    {
        const unsigned char* src = g_Wo + (size_t)chunk * 65536 + 32768 + t * 128;
        u32 dst = sb + OWO + 32768 + t * 128;
        #pragma unroll
        for (int i = 0; i < 8; i++) cp16(dst + 16 * i, src + 16 * i);
        asm volatile("cp.async.commit_group;");
    }

    {
        int row = t >> 2, kq = (t & 3) * 32;
        const float4* rr = (const float4*)(g_rp + (size_t)(b0 + row) * H + kq);
        #pragma unroll
        for (int i = 0; i < 8; i++) {
            float4 v = rr[i];
            int col0 = kq + 4 * i;
            u32 off = swz256(row, 2 * col0);
            __nv_bfloat16 x0, x1, y0, y1;
            x0 = __float2bfloat16(v.x); x1 = __float2bfloat16(v.x - __bfloat162float(x0));
            y0 = __float2bfloat16(v.y); y1 = __float2bfloat16(v.y - __bfloat162float(y0));
            *(u32*)(smc + ORP + off)         = pack_bf2(x0, y0);
            *(u32*)(smc + ORP + 16384 + off) = pack_bf2(x1, y1);
            x0 = __float2bfloat16(v.z); x1 = __float2bfloat16(v.z - __bfloat162float(x0));
            y0 = __float2bfloat16(v.w); y1 = __float2bfloat16(v.w - __bfloat162float(y0));
            *(u32*)(smc + ORP + off + 4)         = pack_bf2(x0, y0);
            *(u32*)(smc + ORP + 16384 + off + 4) = pack_bf2(x1, y1);
        }
    }
    asm volatile("cp.async.wait_group 1;");
    __syncthreads();

    const int m0   = (w >> 1) * 16;
    const int n0   = (w & 1) * 64;
    const int lg   = lane >> 3;
    const int rsel = (lane & 7) + ((lg & 1) << 3);
    const int kbs  = (lg >> 1) << 4;
    const int frow = lane >> 2;
    const int fcol = 2 * (lane & 3);

    float acc[8][4];
    #pragma unroll
    for (int nt = 0; nt < 8; nt++)
        #pragma unroll
        for (int q = 0; q < 4; q++) acc[nt][q] = 0.f;

    const int passA[3] = {1, 0, 0};
    const int passW[3] = {0, 0, 1};
    #pragma unroll
    for (int pp = 0; pp < 3; pp++) {
        if (pp == 2) {
            asm volatile("cp.async.wait_group 0;");
            __syncthreads();
        }
        const u32 Ab = sb + ORP + passA[pp] * 16384;
        const u32 Bb = sb + OWO + passW[pp] * 32768;
        #pragma unroll
        for (int k16 = 0; k16 < 8; k16++) {
            const int kb = k16 * 32 + kbs;
            u32 a[4], q[4][4];
            ldsm_x4(a, Ab + swz256(m0 + rsel, kb));
            #pragma unroll
            for (int nt2 = 0; nt2 < 4; nt2++)
                ldsm_x4(q[nt2], Bb + swz256(n0 + nt2 * 16 + rsel, kb));
            #pragma unroll
            for (int nt = 0; nt < 8; nt++)
                mma16816(acc[nt], a, q[nt >> 1][nt & 1], q[nt >> 1][2 + (nt & 1)]);
        }
    }

    #pragma unroll
    for (int nt = 0; nt < 8; nt++) {
        int col = v0 + n0 + nt * 8 + fcol;
        float bo0 = bout[col], bo1 = bout[col + 1];
        #pragma unroll
        for (int half = 0; half < 2; half++) {
            int row = b0 + m0 + frow + half * 8;
            float2 o2 = make_float2(acc[nt][2 * half + 0] + bo0,
                                    acc[nt][2 * half + 1] + bo1);
            *(float2*)(out + (size_t)row * V + col) = o2;
        }
    }
}

// ---------------------------------------------------------------------------
extern "C" void kernel_launch(void* const* d_in, const int* in_sizes, int n_in,
                              void* d_out, int out_size)
{
    const int*   seq   = (const int*)  d_in[0];
    const float* embed = (const float*)d_in[1];
    const float* W1    = (const float*)d_in[2];
    const float* b1    = (const float*)d_in[3];
    const float* W2    = (const float*)d_in[4];
    const float* b2    = (const float*)d_in[5];
    const float* gamma = (const float*)d_in[6];
    const float* beta  = (const float*)d_in[7];
    const float* Wrp   = (const float*)d_in[8];
    const float* brp   = (const float*)d_in[9];
    const float* Wout  = (const float*)d_in[10];
    const float* bout  = (const float*)d_in[11];
    float* out = (float*)d_out;

    cudaFuncSetAttribute(encode_mma_kernel,
                         cudaFuncAttributeMaxDynamicSharedMemorySize, ENC_SMEM);
    cudaFuncSetAttribute(out_mma_kernel,
                         cudaFuncAttributeMaxDynamicSharedMemorySize, OUT_SMEM);
    cudaFuncSetAttribute(prep2_kernel,
                         cudaFuncAttributeMaxDynamicSharedMemorySize, P2_SMEM);

    prep_kernel<<<256, 256>>>(W1, W2);
    prep2_kernel<<<250, 256, P2_SMEM>>>(Wout);
    encode_mma_kernel<<<BL / TOK, 256, ENC_SMEM>>>(seq, embed, b1, b2, gamma, beta);
    scan_kernel<<<B, 128>>>(Wrp, brp);
    dim3 og(250, 4);
    out_mma_kernel<<<og, 256, OUT_SMEM>>>(bout, out);
}